// round 3
// baseline (speedup 1.0000x reference)
#include <cuda_runtime.h>
#include <cstdint>

// NMS_20933670600803
// heatmap: (B, 1, 14, 14) float32, B = 131072
// output : (m1, m2) each (B, 1, 14, 14) float32, concatenated: [m1 | m2]
//
// One warp per batch item. Each lane owns elements {lane + 32k : k<7, idx<196}.
// 4x (argmax -> window suppress), then farthest-pair over 6 pairs, then
// Voronoi masks. Argmax tie-break = smallest index (matches jnp.argmax).

#define LENGTH    14
#define NPIX      196          // 14*14
#define THRESH    0.6f
#define WARPS_PER_BLOCK 8
#define THREADS   (WARPS_PER_BLOCK * 32)

__global__ __launch_bounds__(THREADS)
void nms_masks_kernel(const float* __restrict__ hm,
                      float* __restrict__ out,
                      int B)
{
    const int warp = (blockIdx.x * WARPS_PER_BLOCK) + (threadIdx.x >> 5);
    const int lane = threadIdx.x & 31;
    if (warp >= B) return;

    const float* __restrict__ p = hm + (size_t)warp * NPIX;

    // Per-lane element coordinates (compile-time unrolled, idx = lane + 32k)
    float v[7];
    int   eu[7], ev[7];          // row (idx/14), col (idx%14)
    bool  live[7];
#pragma unroll
    for (int k = 0; k < 7; k++) {
        int i = lane + 32 * k;
        live[k] = (i < NPIX);
        float x = live[k] ? __ldg(p + i) : 0.0f;
        v[k]  = (x > THRESH) ? x : 0.0f;
        eu[k] = i / LENGTH;
        ev[k] = i % LENGTH;
    }

    int px[4], py[4];

#pragma unroll
    for (int it = 0; it < 4; it++) {
        // ---- local argmax (ascending index, strict > keeps first max) ----
        float bv = -1.0f;
        int   bi = 0;
#pragma unroll
        for (int k = 0; k < 7; k++) {
            int i = lane + 32 * k;
            if (live[k] && v[k] > bv) { bv = v[k]; bi = i; }
        }
        // ---- warp argmax, tie -> smaller index ----
#pragma unroll
        for (int off = 16; off > 0; off >>= 1) {
            float ov = __shfl_xor_sync(0xffffffffu, bv, off);
            int   oi = __shfl_xor_sync(0xffffffffu, bi, off);
            if (ov > bv || (ov == bv && oi < bi)) { bv = ov; bi = oi; }
        }

        const int x = bi / LENGTH;
        const int y = bi % LENGTH;
        px[it] = x; py[it] = y;

        // ---- suppress window: rows [max(x-5,0), min(x+5,15)), same for cols ----
        const int x1 = max(x - 5, 0), x2 = min(x + 5, 15);
        const int y1 = max(y - 5, 0), y2 = min(y + 5, 15);
#pragma unroll
        for (int k = 0; k < 7; k++) {
            bool inwin = (eu[k] >= x1) & (eu[k] < x2) & (ev[k] >= y1) & (ev[k] < y2);
            if (inwin) v[k] = 0.0f;
        }
    }

    // ---- farthest pair among 4 peaks (6 pairs, first-tie argmax) ----
    const int pa[6] = {0, 0, 0, 1, 1, 2};
    const int pb[6] = {1, 2, 3, 2, 3, 3};
    int bd = -1, bp = 0;
#pragma unroll
    for (int q = 0; q < 6; q++) {
        int dx = px[pb[q]] - px[pa[q]];
        int dy = py[pb[q]] - py[pa[q]];
        int d  = dx * dx + dy * dy;
        if (d > bd) { bd = d; bp = q; }
    }
    const int ax = px[pa[bp]], ay = py[pa[bp]];
    const int bx = px[pb[bp]], by = py[pb[bp]];

    // ---- emit masks ----
    float* __restrict__ o1 = out + (size_t)warp * NPIX;
    float* __restrict__ o2 = out + (size_t)B * NPIX + (size_t)warp * NPIX;
#pragma unroll
    for (int k = 0; k < 7; k++) {
        if (!live[k]) continue;
        int i  = lane + 32 * k;
        int du1 = eu[k] - ax, dv1 = ev[k] - ay;
        int du2 = eu[k] - bx, dv2 = ev[k] - by;
        int d1 = du1 * du1 + dv1 * dv1;
        int d2 = du2 * du2 + dv2 * dv2;
        float m1 = (d1 < d2) ? 1.0f : 0.0f;
        o1[i] = m1;
        o2[i] = 1.0f - m1;
    }
}

extern "C" void kernel_launch(void* const* d_in, const int* in_sizes, int n_in,
                              void* d_out, int out_size)
{
    const float* hm = (const float*)d_in[0];
    float* out = (float*)d_out;
    const int B = in_sizes[0] / NPIX;   // 131072
    const int grid = (B + WARPS_PER_BLOCK - 1) / WARPS_PER_BLOCK;
    nms_masks_kernel<<<grid, THREADS>>>(hm, out, B);
}

// round 4
// speedup vs baseline: 1.6487x; 1.6487x over previous
#include <cuda_runtime.h>
#include <cstdint>

// NMS_20933670600803
// heatmap: (B, 1, 14, 14) float32, B = 131072
// output : [m1 | m2], each (B, 1, 14, 14) float32
//
// One warp per batch item, float4 I/O (49 float4 per 196-elem map).
// Lane j owns element groups {4j..4j+3} and, for j<17, {128+4j..128+4j+3}.
//
// Argmax via packed u32 keys:
//   value v in (0.6, 1.0)  ->  key = ((fbits(v) - 0x3F000000) << 8) | (255 - idx)
//   value v == 0 (below threshold / suppressed) -> key = 255 - idx
// Unsigned max over keys == (max value, tie -> smallest index), exactly
// matching jnp.argmax first-occurrence semantics. Warp reduction is a single
// REDUX.MAX.U32 (__reduce_max_sync). Suppression = key &= 0xFF.
//
// Voronoi mask linearized: d1<d2  <=>  2(bx-ax)*eu + 2(by-ay)*ev < bx^2+by^2-ax^2-ay^2.

#define NPIX  196
#define NVEC  49          // 196 / 4
#define WPB   8
#define THREADS (WPB * 32)

__global__ __launch_bounds__(THREADS)
void nms_masks_kernel(const float4* __restrict__ hm,
                      float4* __restrict__ out,
                      int B)
{
    const int warp = blockIdx.x * WPB + (threadIdx.x >> 5);
    const int lane = threadIdx.x & 31;
    if (warp >= B) return;

    const float4* __restrict__ p = hm + (size_t)warp * NVEC;

    float4 va = p[lane];                          // elements 4*lane .. 4*lane+3 (always valid: <=127)
    const bool has2 = (lane < 17);                // elements 128+4*lane .. (valid while <196)
    float4 vb = make_float4(0.f, 0.f, 0.f, 0.f);
    if (has2) vb = p[lane + 32];

    const int i0 = 4 * lane;
    const int i1 = 128 + 4 * lane;

    unsigned key[8];
    int eu[8], ev[8];
    {
        float vals[8] = {va.x, va.y, va.z, va.w, vb.x, vb.y, vb.z, vb.w};
#pragma unroll
        for (int c = 0; c < 8; c++) {
            int  i     = (c < 4) ? (i0 + c) : (i1 + c - 4);
            bool valid = (c < 4) || has2;
            unsigned kz = valid ? (255u - (unsigned)i) : 0u;
            float    x  = vals[c];
            unsigned fb = __float_as_uint(x);
            key[c] = (x > 0.6f) ? ((((fb - 0x3F000000u)) << 8) | kz) : kz;
            eu[c]  = i / 14;
            ev[c]  = i - 14 * eu[c];
        }
    }

    int px[4], py[4];

#pragma unroll
    for (int it = 0; it < 4; it++) {
        // local max over 8 keys (7 IMNMX.U32)
        unsigned m01 = max(key[0], key[1]);
        unsigned m23 = max(key[2], key[3]);
        unsigned m45 = max(key[4], key[5]);
        unsigned m67 = max(key[6], key[7]);
        unsigned m   = max(max(m01, m23), max(m45, m67));
        // warp max: single REDUX instruction, result broadcast to all lanes
        unsigned w = __reduce_max_sync(0xffffffffu, m);

        const int bi = 255 - (int)(w & 0xFFu);
        const int x  = bi / 14;
        const int y  = bi - 14 * x;
        px[it] = x; py[it] = y;

        // suppress window rows [max(x-5,0), min(x+5,15)), cols likewise
        const int x1 = max(x - 5, 0);
        const int y1 = max(y - 5, 0);
        const unsigned dx = (unsigned)(min(x + 5, 15) - x1);
        const unsigned dy = (unsigned)(min(y + 5, 15) - y1);
#pragma unroll
        for (int c = 0; c < 8; c++) {
            bool inwin = ((unsigned)(eu[c] - x1) < dx) & ((unsigned)(ev[c] - y1) < dy);
            if (inwin) key[c] &= 0xFFu;           // -> zero-value key (keeps tie index)
        }
    }

    // farthest pair among 4 peaks (6 pairs, first-tie argmax)
    const int pa[6] = {0, 0, 0, 1, 1, 2};
    const int pb[6] = {1, 2, 3, 2, 3, 3};
    int bd = -1, ax = 0, ay = 0, bx = 0, by = 0;
#pragma unroll
    for (int q = 0; q < 6; q++) {
        int ddx = px[pb[q]] - px[pa[q]];
        int ddy = py[pb[q]] - py[pa[q]];
        int d   = ddx * ddx + ddy * ddy;
        if (d > bd) {
            bd = d;
            ax = px[pa[q]]; ay = py[pa[q]];
            bx = px[pb[q]]; by = py[pb[q]];
        }
    }

    // linearized Voronoi: d1<d2  <=>  Cx*eu + Cy*ev < Cc
    const int Cx = 2 * (bx - ax);
    const int Cy = 2 * (by - ay);
    const int Cc = bx * bx + by * by - ax * ax - ay * ay;

    float m1v[8];
#pragma unroll
    for (int c = 0; c < 8; c++)
        m1v[c] = (Cx * eu[c] + Cy * ev[c] < Cc) ? 1.0f : 0.0f;

    float4* __restrict__ o1 = out + (size_t)warp * NVEC;
    float4* __restrict__ o2 = out + (size_t)B * NVEC + (size_t)warp * NVEC;

    o1[lane] = make_float4(m1v[0], m1v[1], m1v[2], m1v[3]);
    o2[lane] = make_float4(1.0f - m1v[0], 1.0f - m1v[1], 1.0f - m1v[2], 1.0f - m1v[3]);
    if (has2) {
        o1[lane + 32] = make_float4(m1v[4], m1v[5], m1v[6], m1v[7]);
        o2[lane + 32] = make_float4(1.0f - m1v[4], 1.0f - m1v[5], 1.0f - m1v[6], 1.0f - m1v[7]);
    }
}

extern "C" void kernel_launch(void* const* d_in, const int* in_sizes, int n_in,
                              void* d_out, int out_size)
{
    const float4* hm  = (const float4*)d_in[0];
    float4*       out = (float4*)d_out;
    const int B = in_sizes[0] / NPIX;             // 131072
    const int grid = (B + WPB - 1) / WPB;
    nms_masks_kernel<<<grid, THREADS>>>(hm, out, B);
}